// round 5
// baseline (speedup 1.0000x reference)
#include <cuda_runtime.h>
#include <cuda_bf16.h>
#include <math.h>

#define BATCH 65536
#define NPAIR 32768
#define DIM   256
#define FULLM 0xffffffffu

// smem: att_w1 transposed [16][512] fp32 (32768B) + pred_w1 packed bf16 (12288B)
#define SW1_FLOATS (16 * 512)
#define SWP_HALFS  (8 * 3 * 256)
#define SMEM_BYTES (SW1_FLOATS * 4 + SWP_HALFS * 2)   // 45056 B

typedef unsigned long long u64;

// ---- packed f32x2 helpers (sm_103a FFMA2 path, PTX-only) ----
__device__ __forceinline__ u64 pk(float x, float y) {
    u64 r; asm("mov.b64 %0,{%1,%2};" : "=l"(r) : "f"(x), "f"(y)); return r;
}
__device__ __forceinline__ u64 dup2(float x) {
    u64 r; asm("mov.b64 %0,{%1,%1};" : "=l"(r) : "f"(x)); return r;
}
__device__ __forceinline__ void upk(u64 p, float& x, float& y) {
    asm("mov.b64 {%0,%1},%2;" : "=f"(x), "=f"(y) : "l"(p));
}
__device__ __forceinline__ u64 ffma2(u64 a, u64 b, u64 c) {
    u64 d; asm("fma.rn.f32x2 %0,%1,%2,%3;" : "=l"(d) : "l"(a), "l"(b), "l"(c)); return d;
}
__device__ __forceinline__ u64 fadd2(u64 a, u64 b) {
    u64 d; asm("add.rn.f32x2 %0,%1,%2;" : "=l"(d) : "l"(a), "l"(b)); return d;
}
__device__ __forceinline__ u64 fmul2(u64 a, u64 b) {
    u64 d; asm("mul.rn.f32x2 %0,%1,%2;" : "=l"(d) : "l"(a), "l"(b)); return d;
}

// fold 16 packed values across 32 lanes -> lane gets full packed sum of value (lane&15)
__device__ __forceinline__ u64 fold16p(u64* A, int lane) {
    #pragma unroll
    for (int d = 8; d >= 1; d >>= 1) {
        const bool hi = (lane & d) != 0;
        #pragma unroll
        for (int i = 0; i < d; i++) {
            u64 send = hi ? A[i] : A[i + d];
            u64 recv = __shfl_xor_sync(FULLM, send, d);
            A[i] = fadd2(hi ? A[i + d] : A[i], recv);
        }
    }
    u64 v = A[0];
    v = fadd2(v, __shfl_xor_sync(FULLM, v, 16));
    return v;
}

// fold 8 packed values across 32 lanes -> lane gets full packed sum of value (lane&7)
__device__ __forceinline__ u64 fold8p(u64* A, int lane) {
    #pragma unroll
    for (int d = 4; d >= 1; d >>= 1) {
        const bool hi = (lane & d) != 0;
        #pragma unroll
        for (int i = 0; i < d; i++) {
            u64 send = hi ? A[i] : A[i + d];
            u64 recv = __shfl_xor_sync(FULLM, send, d);
            A[i] = fadd2(hi ? A[i + d] : A[i], recv);
        }
    }
    u64 v = A[0];
    v = fadd2(v, __shfl_xor_sync(FULLM, v, 8));
    v = fadd2(v, __shfl_xor_sync(FULLM, v, 16));
    return v;
}

__global__ __launch_bounds__(128, 3)
void agree_kernel(
    const int*   __restrict__ group_inputs,
    const int*   __restrict__ item_inputs,
    const int*   __restrict__ group_members,
    const float* __restrict__ user_emb,
    const float* __restrict__ item_emb,
    const float* __restrict__ group_emb,
    const float* __restrict__ att_w1,
    const float* __restrict__ att_b1,
    const float* __restrict__ att_w2,
    const float* __restrict__ att_b2,
    const float* __restrict__ cls_w,
    const float* __restrict__ cls_b,
    const float* __restrict__ pred_w1,
    const float* __restrict__ pred_b1,
    const float* __restrict__ pred_w2,
    const float* __restrict__ pred_b2,
    float*       __restrict__ out)
{
    extern __shared__ float sm[];
    float* sw1 = sm;                                        // [16][512] fp32
    __nv_bfloat16* swp = (__nv_bfloat16*)(sm + SW1_FLOATS); // packed bf16

    const int tid = threadIdx.x;

    for (int i = tid; i < 512 * 16; i += blockDim.x) {
        int d = i >> 4, f = i & 15;
        sw1[f * 512 + d] = att_w1[i];
    }
    // pred_w1 bf16 packed: half index = k*768 + r*256 + lane*8 + ii
    // src j = r*256 + (ii>=4 ? 128 : 0) + 4*lane + (ii&3), value pred_w1[j*8+k]
    for (int i = tid; i < SWP_HALFS; i += blockDim.x) {
        int k   = i / 768;
        int rem = i - k * 768;
        int r   = rem >> 8;
        int q   = rem & 255;
        int ln  = q >> 3;
        int ii  = q & 7;
        int j   = r * 256 + ((ii & 4) ? 128 : 0) + 4 * ln + (ii & 3);
        swp[i] = __float2bfloat16(pred_w1[j * 8 + k]);
    }
    __syncthreads();

    const int lane  = tid & 31;
    const int gwarp = blockIdx.x * 4 + (tid >> 5);
    const int nwarp = gridDim.x * 4;

    // per-lane constants
    const int l3 = lane & 3;
    float b1c[4], w2c[4];
    #pragma unroll
    for (int c = 0; c < 4; c++) {
        b1c[c] = __ldg(att_b1 + c * 4 + l3);
        w2c[c] = __ldg(att_w2 + c * 4 + l3);
    }
    const float pbk  = __ldg(pred_b1 + (lane & 7));
    const float pwk  = __ldg(pred_w2 + (lane & 7));
    const float b2v  = __ldg(att_b2);
    const float clw0 = __ldg(cls_w), clw1 = __ldg(cls_w + 1);
    const float clb0 = __ldg(cls_b), clb1 = __ldg(cls_b + 1);
    const float pb2  = __ldg(pred_b2);

    for (int p = gwarp; p < NPAIR; p += nwarp) {
        const int b0 = 2 * p, b1 = 2 * p + 1;
        const int gidA = group_inputs[b0], gidB = group_inputs[b1];
        const int iidA = item_inputs[b0],  iidB = item_inputs[b1];

        // gather both elements' rows, pack across the pair (e0=lo, e1=hi)
        u64 pmem[4][8], pit[8];
        {
            const int4 mA = *(const int4*)(group_members + gidA * 4);
            const int4 mB = *(const int4*)(group_members + gidB * 4);
            int midsA[4] = {mA.x, mA.y, mA.z, mA.w};
            int midsB[4] = {mB.x, mB.y, mB.z, mB.w};
            #pragma unroll
            for (int s = 0; s < 4; s++) {
                const float4* rA = (const float4*)(user_emb + (size_t)midsA[s] * DIM);
                const float4* rB = (const float4*)(user_emb + (size_t)midsB[s] * DIM);
                float4 a0 = rA[lane], a1 = rA[32 + lane];
                float4 c0 = rB[lane], c1 = rB[32 + lane];
                pmem[s][0] = pk(a0.x, c0.x); pmem[s][1] = pk(a0.y, c0.y);
                pmem[s][2] = pk(a0.z, c0.z); pmem[s][3] = pk(a0.w, c0.w);
                pmem[s][4] = pk(a1.x, c1.x); pmem[s][5] = pk(a1.y, c1.y);
                pmem[s][6] = pk(a1.z, c1.z); pmem[s][7] = pk(a1.w, c1.w);
            }
            const float4* iA = (const float4*)(item_emb + (size_t)iidA * DIM);
            const float4* iB = (const float4*)(item_emb + (size_t)iidB * DIM);
            float4 a0 = iA[lane], a1 = iA[32 + lane];
            float4 c0 = iB[lane], c1 = iB[32 + lane];
            pit[0] = pk(a0.x, c0.x); pit[1] = pk(a0.y, c0.y);
            pit[2] = pk(a0.z, c0.z); pit[3] = pk(a0.w, c0.w);
            pit[4] = pk(a1.x, c1.x); pit[5] = pk(a1.y, c1.y);
            pit[6] = pk(a1.z, c1.z); pit[7] = pk(a1.w, c1.w);
        }

        // ---- attention MLP, f chunked by 4, packed across pair ----
        u64 plogit = dup2(b2v);
        #pragma unroll
        for (int c = 0; c < 4; c++) {
            u64 pA[16];
            #pragma unroll
            for (int fi = 0; fi < 4; fi++) {
                const float* wrow = sw1 + (c * 4 + fi) * 512;
                float4 wm0 = *(const float4*)(wrow + 4 * lane);
                float4 wm1 = *(const float4*)(wrow + 128 + 4 * lane);
                float4 wi0 = *(const float4*)(wrow + 256 + 4 * lane);
                float4 wi1 = *(const float4*)(wrow + 384 + 4 * lane);

                u64 t = fmul2(pit[0], dup2(wi0.x));
                t = ffma2(pit[1], dup2(wi0.y), t);
                t = ffma2(pit[2], dup2(wi0.z), t);
                t = ffma2(pit[3], dup2(wi0.w), t);
                t = ffma2(pit[4], dup2(wi1.x), t);
                t = ffma2(pit[5], dup2(wi1.y), t);
                t = ffma2(pit[6], dup2(wi1.z), t);
                t = ffma2(pit[7], dup2(wi1.w), t);

                u64 w0 = dup2(wm0.x), w1 = dup2(wm0.y), w2 = dup2(wm0.z), w3 = dup2(wm0.w);
                u64 w4 = dup2(wm1.x), w5 = dup2(wm1.y), w6 = dup2(wm1.z), w7 = dup2(wm1.w);
                #pragma unroll
                for (int s = 0; s < 4; s++) {
                    u64 a = t;
                    a = ffma2(pmem[s][0], w0, a);
                    a = ffma2(pmem[s][1], w1, a);
                    a = ffma2(pmem[s][2], w2, a);
                    a = ffma2(pmem[s][3], w3, a);
                    a = ffma2(pmem[s][4], w4, a);
                    a = ffma2(pmem[s][5], w5, a);
                    a = ffma2(pmem[s][6], w6, a);
                    a = ffma2(pmem[s][7], w7, a);
                    pA[s * 4 + fi] = a;
                }
            }
            u64 pr = fold16p(pA, lane);   // lane: s=(lane&15)>>2, f=c*4+(lane&3)
            float r0, r1; upk(pr, r0, r1);
            float cv0 = fmaxf(r0 + b1c[c], 0.f) * w2c[c];
            float cv1 = fmaxf(r1 + b1c[c], 0.f) * w2c[c];
            u64 cvp = pk(cv0, cv1);
            cvp = fadd2(cvp, __shfl_xor_sync(FULLM, cvp, 1));
            cvp = fadd2(cvp, __shfl_xor_sync(FULLM, cvp, 2));
            plogit = fadd2(plogit, cvp);
        }
        float ll[2]; upk(plogit, ll[0], ll[1]);

        // softmax / argmax / classifier per element (lane s*4 holds member s)
        float wt[2][4];
        int   pc[2];
        float cw[2][4];
        #pragma unroll
        for (int e = 0; e < 2; e++) {
            float logit[4];
            #pragma unroll
            for (int s = 0; s < 4; s++)
                logit[s] = __shfl_sync(FULLM, ll[e], s * 4);

            float mx = logit[0]; int ix = 0;
            #pragma unroll
            for (int s = 1; s < 4; s++)
                if (logit[s] > mx) { mx = logit[s]; ix = s; }

            float ev[4], sum = 0.f;
            #pragma unroll
            for (int s = 0; s < 4; s++) { ev[s] = expf(logit[s] - mx); sum += ev[s]; }
            float inv = 1.f / sum;
            #pragma unroll
            for (int s = 0; s < 4; s++) wt[e][s] = ev[s] * inv;

            float s0 = inv * clw0 + clb0;   // wt[ix] == inv exactly
            float s1 = inv * clw1 + clb1;
            pc[e] = (s1 > s0) ? 1 : 0;
            #pragma unroll
            for (int s = 0; s < 4; s++)
                cw[e][s] = pc[e] ? ((s == ix) ? 1.f : 0.f) : wt[e][s];
        }

        // ---- epilogue packed: g = sum_s cw*mem + grp ; el = g*it ----
        u64 pcw[4];
        #pragma unroll
        for (int s = 0; s < 4; s++) pcw[s] = pk(cw[0][s], cw[1][s]);

        u64 pgv[8], pel[8];
        {
            const float4* gA = (const float4*)(group_emb + (size_t)gidA * DIM);
            const float4* gB = (const float4*)(group_emb + (size_t)gidB * DIM);
            #pragma unroll
            for (int g = 0; g < 2; g++) {
                float4 ga = gA[g * 32 + lane];
                float4 gb = gB[g * 32 + lane];
                const float* gaf = (const float*)&ga;
                const float* gbf = (const float*)&gb;
                #pragma unroll
                for (int c = 0; c < 4; c++) {
                    int j = g * 4 + c;
                    u64 t = fmul2(pmem[0][j], pcw[0]);
                    t = ffma2(pmem[1][j], pcw[1], t);
                    t = ffma2(pmem[2][j], pcw[2], t);
                    t = ffma2(pmem[3][j], pcw[3], t);
                    t = fadd2(t, pk(gaf[c], gbf[c]));
                    pgv[j] = t;
                    pel[j] = fmul2(t, pit[j]);
                }
            }
        }

        // ---- prediction MLP packed across pair ----
        u64 pacc[8];
        #pragma unroll
        for (int k = 0; k < 8; k++) {
            u64 a = 0ull;   // (0.f, 0.f)
            #pragma unroll
            for (int r = 0; r < 3; r++) {
                const u64* val = (r == 0) ? pel : (r == 1) ? pgv : pit;
                uint4 u = *(const uint4*)(swp + (k * 3 + r) * 256 + lane * 8);
                const __nv_bfloat162* h2 = (const __nv_bfloat162*)&u;
                float2 p0 = __bfloat1622float2(h2[0]);
                float2 p1 = __bfloat1622float2(h2[1]);
                float2 p2 = __bfloat1622float2(h2[2]);
                float2 p3 = __bfloat1622float2(h2[3]);
                a = ffma2(val[0], dup2(p0.x), a);
                a = ffma2(val[1], dup2(p0.y), a);
                a = ffma2(val[2], dup2(p1.x), a);
                a = ffma2(val[3], dup2(p1.y), a);
                a = ffma2(val[4], dup2(p2.x), a);
                a = ffma2(val[5], dup2(p2.y), a);
                a = ffma2(val[6], dup2(p3.x), a);
                a = ffma2(val[7], dup2(p3.y), a);
            }
            pacc[k] = a;
        }

        u64 pv = fold8p(pacc, lane);   // lane holds packed acc for k = lane&7
        float v0, v1; upk(pv, v0, v1);
        float hz0 = fmaxf(v0 + pbk, 0.f) * pwk;
        float hz1 = fmaxf(v1 + pbk, 0.f) * pwk;
        u64 hzp = pk(hz0, hz1);
        hzp = fadd2(hzp, __shfl_xor_sync(FULLM, hzp, 1));
        hzp = fadd2(hzp, __shfl_xor_sync(FULLM, hzp, 2));
        hzp = fadd2(hzp, __shfl_xor_sync(FULLM, hzp, 4));
        float z0, z1; upk(hzp, z0, z1);
        float y[2];
        y[0] = 1.f / (1.f + expf(-(z0 + pb2)));
        y[1] = 1.f / (1.f + expf(-(z1 + pb2)));

        if (lane < 2) {
            const int e = lane;
            const int b = 2 * p + e;
            out[b] = y[e];
            *(float4*)(out + BATCH + 4 * b) = make_float4(wt[e][0], wt[e][1], wt[e][2], wt[e][3]);
            out[5 * BATCH + b] = (float)pc[e];
        }
    }
}

extern "C" void kernel_launch(void* const* d_in, const int* in_sizes, int n_in,
                              void* d_out, int out_size)
{
    (void)in_sizes; (void)n_in; (void)out_size;
    cudaFuncSetAttribute(agree_kernel,
                         cudaFuncAttributeMaxDynamicSharedMemorySize, SMEM_BYTES);
    agree_kernel<<<444, 128, SMEM_BYTES>>>(
        (const int*)d_in[0],  (const int*)d_in[1],  (const int*)d_in[2],
        (const float*)d_in[3], (const float*)d_in[4], (const float*)d_in[5],
        (const float*)d_in[6], (const float*)d_in[7], (const float*)d_in[8],
        (const float*)d_in[9], (const float*)d_in[10], (const float*)d_in[11],
        (const float*)d_in[12], (const float*)d_in[13], (const float*)d_in[14],
        (const float*)d_in[15],
        (float*)d_out);
}

// round 6
// speedup vs baseline: 1.2938x; 1.2938x over previous
#include <cuda_runtime.h>
#include <cuda_bf16.h>
#include <math.h>

#define BATCH 65536
#define NPAIR 32768
#define DIM   256
#define FULLM 0xffffffffu

// smem: att_w1 transposed [16][512] fp32 (32768B) + pred_w1 packed bf16 (12288B)
#define SW1_FLOATS (16 * 512)
#define SWP_HALFS  (8 * 3 * 256)
#define SMEM_BYTES (SW1_FLOATS * 4 + SWP_HALFS * 2)   // 45056 B

__device__ __forceinline__ float dot4(float4 a, float4 b) {
    return a.x * b.x + a.y * b.y + a.z * b.z + a.w * b.w;
}

// SEL-free fold: A[i] holds partial of value (i ^ (lane&15)).
// Returns full sum of value (lane&15) on every lane.
__device__ __forceinline__ float fold16x(float* A) {
    #pragma unroll
    for (int d = 8; d >= 1; d >>= 1)
        #pragma unroll
        for (int i = 0; i < d; i++)
            A[i] += __shfl_xor_sync(FULLM, A[i + d], d);
    float v = A[0];
    v += __shfl_xor_sync(FULLM, v, 16);
    return v;
}

// SEL-free fold: A[i] holds partial of value (i ^ (lane&7)).
// Returns full sum of value (lane&7) on every lane.
__device__ __forceinline__ float fold8x(float* A) {
    #pragma unroll
    for (int d = 4; d >= 1; d >>= 1)
        #pragma unroll
        for (int i = 0; i < d; i++)
            A[i] += __shfl_xor_sync(FULLM, A[i + d], d);
    float v = A[0];
    v += __shfl_xor_sync(FULLM, v, 8);
    v += __shfl_xor_sync(FULLM, v, 16);
    return v;
}

// permute a 4-entry int array: out[s] = in[s ^ p]  (p in 0..3), via 2-level select
__device__ __forceinline__ void perm4i(const int* in, int* out, int p) {
    int t0 = (p & 1) ? in[1] : in[0];
    int t1 = (p & 1) ? in[0] : in[1];
    int t2 = (p & 1) ? in[3] : in[2];
    int t3 = (p & 1) ? in[2] : in[3];
    out[0] = (p & 2) ? t2 : t0;
    out[1] = (p & 2) ? t3 : t1;
    out[2] = (p & 2) ? t0 : t2;
    out[3] = (p & 2) ? t1 : t3;
}

__device__ __forceinline__ void perm4f(const float* in, float* out, int p) {
    float t0 = (p & 1) ? in[1] : in[0];
    float t1 = (p & 1) ? in[0] : in[1];
    float t2 = (p & 1) ? in[3] : in[2];
    float t3 = (p & 1) ? in[2] : in[3];
    out[0] = (p & 2) ? t2 : t0;
    out[1] = (p & 2) ? t3 : t1;
    out[2] = (p & 2) ? t0 : t2;
    out[3] = (p & 2) ? t1 : t3;
}

__global__ __launch_bounds__(128, 3)
void agree_kernel(
    const int*   __restrict__ group_inputs,
    const int*   __restrict__ item_inputs,
    const int*   __restrict__ group_members,
    const float* __restrict__ user_emb,
    const float* __restrict__ item_emb,
    const float* __restrict__ group_emb,
    const float* __restrict__ att_w1,
    const float* __restrict__ att_b1,
    const float* __restrict__ att_w2,
    const float* __restrict__ att_b2,
    const float* __restrict__ cls_w,
    const float* __restrict__ cls_b,
    const float* __restrict__ pred_w1,
    const float* __restrict__ pred_b1,
    const float* __restrict__ pred_w2,
    const float* __restrict__ pred_b2,
    float*       __restrict__ out)
{
    extern __shared__ float sm[];
    float* sw1 = sm;                                        // [16][512] fp32
    __nv_bfloat16* swp = (__nv_bfloat16*)(sm + SW1_FLOATS); // packed bf16

    const int tid = threadIdx.x;

    // stage att_w1 transposed: sw1[f*512 + d] = att_w1[d*16 + f]
    for (int i = tid; i < 512 * 16; i += blockDim.x) {
        int d = i >> 4, f = i & 15;
        sw1[f * 512 + d] = att_w1[i];
    }
    // pred_w1 bf16 packed: half index = k*768 + r*256 + lane*8 + ii
    // src j = r*256 + (ii>=4 ? 128 : 0) + 4*lane + (ii&3), value pred_w1[j*8+k]
    for (int i = tid; i < SWP_HALFS; i += blockDim.x) {
        int k   = i / 768;
        int rem = i - k * 768;
        int r   = rem >> 8;
        int q   = rem & 255;
        int ln  = q >> 3;
        int ii  = q & 7;
        int j   = r * 256 + ((ii & 4) ? 128 : 0) + 4 * ln + (ii & 3);
        swp[i] = __float2bfloat16(pred_w1[j * 8 + k]);
    }
    __syncthreads();

    const int lane  = tid & 31;
    const int gwarp = blockIdx.x * 4 + (tid >> 5);
    const int nwarp = gridDim.x * 4;

    const int q  = lane & 3;           // f-permutation within chunk
    const int p  = (lane >> 2) & 3;    // member (s) permutation
    const int l7 = lane & 7;           // pred k slot base
    const int qs = q << 9;             // q*512 for XOR addressing

    // per-lane constants (final fold mapping identical to unpermuted version)
    float b1c[4], w2c[4];
    #pragma unroll
    for (int c = 0; c < 4; c++) {
        b1c[c] = __ldg(att_b1 + c * 4 + q);
        w2c[c] = __ldg(att_w2 + c * 4 + q);
    }
    const float pbk  = __ldg(pred_b1 + l7);
    const float pwk  = __ldg(pred_w2 + l7);
    const float b2v  = __ldg(att_b2);
    const float clw0 = __ldg(cls_w), clw1 = __ldg(cls_w + 1);
    const float clb0 = __ldg(cls_b), clb1 = __ldg(cls_b + 1);
    const float pb2  = __ldg(pred_b2);

    for (int pp = gwarp; pp < NPAIR; pp += nwarp) {
        const int b0 = 2 * pp, b1 = 2 * pp + 1;
        const int gidA = group_inputs[b0], gidB = group_inputs[b1];
        const int iidA = item_inputs[b0],  iidB = item_inputs[b1];

        // member ids, permuted so register slot s holds member (s ^ p)
        int mpA[4], mpB[4];
        {
            const int4 mA = *(const int4*)(group_members + gidA * 4);
            const int4 mB = *(const int4*)(group_members + gidB * 4);
            int rawA[4] = {mA.x, mA.y, mA.z, mA.w};
            int rawB[4] = {mB.x, mB.y, mB.z, mB.w};
            perm4i(rawA, mpA, p);
            perm4i(rawB, mpB, p);
        }

        // gather rows: lane owns d = {4*lane..+3, 128+4*lane..+3}
        float4 mem[2][4][2], it[2][2];
        #pragma unroll
        for (int s = 0; s < 4; s++) {
            const float4* rA = (const float4*)(user_emb + (size_t)mpA[s] * DIM);
            const float4* rB = (const float4*)(user_emb + (size_t)mpB[s] * DIM);
            mem[0][s][0] = rA[lane];  mem[0][s][1] = rA[32 + lane];
            mem[1][s][0] = rB[lane];  mem[1][s][1] = rB[32 + lane];
        }
        {
            const float4* iA = (const float4*)(item_emb + (size_t)iidA * DIM);
            const float4* iB = (const float4*)(item_emb + (size_t)iidB * DIM);
            it[0][0] = iA[lane];  it[0][1] = iA[32 + lane];
            it[1][0] = iB[lane];  it[1][1] = iB[32 + lane];
        }

        // ---- attention MLP: chunks of 4 f, XOR-permuted slots, SEL-free folds ----
        float logit_loc[2] = {b2v, b2v};
        #pragma unroll
        for (int c = 0; c < 4; c++) {
            float A0[16], A1[16];
            #pragma unroll
            for (int fi = 0; fi < 4; fi++) {
                // lane reads weight row f = c*4 + (fi ^ q)
                const float* wrow = sw1 + c * 2048 + (((fi << 9) ^ qs)) + 4 * lane;
                float4 wm0 = *(const float4*)(wrow);
                float4 wm1 = *(const float4*)(wrow + 128);
                float4 wi0 = *(const float4*)(wrow + 256);
                float4 wi1 = *(const float4*)(wrow + 384);
                float itp0 = dot4(it[0][0], wi0) + dot4(it[0][1], wi1);
                float itp1 = dot4(it[1][0], wi0) + dot4(it[1][1], wi1);
                #pragma unroll
                for (int s = 0; s < 4; s++) {
                    A0[s * 4 + fi] = dot4(mem[0][s][0], wm0) + dot4(mem[0][s][1], wm1) + itp0;
                    A1[s * 4 + fi] = dot4(mem[1][s][0], wm0) + dot4(mem[1][s][1], wm1) + itp1;
                }
            }
            // slot i holds value (i ^ (lane&15)); fold -> lane holds value (lane&15)
            {
                float r0 = fold16x(A0);
                float cv = fmaxf(r0 + b1c[c], 0.f) * w2c[c];
                cv += __shfl_xor_sync(FULLM, cv, 1);
                cv += __shfl_xor_sync(FULLM, cv, 2);
                logit_loc[0] += cv;
            }
            {
                float r1 = fold16x(A1);
                float cv = fmaxf(r1 + b1c[c], 0.f) * w2c[c];
                cv += __shfl_xor_sync(FULLM, cv, 1);
                cv += __shfl_xor_sync(FULLM, cv, 2);
                logit_loc[1] += cv;
            }
        }

        // softmax / argmax / classifier per element (lane s*4 holds member s)
        float wt[2][4];
        int   pc[2];
        float cwp[2][4];   // epilogue coefficients, permuted to match memreg slots
        #pragma unroll
        for (int e = 0; e < 2; e++) {
            float logit[4];
            #pragma unroll
            for (int s = 0; s < 4; s++)
                logit[s] = __shfl_sync(FULLM, logit_loc[e], s * 4);

            float mx = logit[0]; int ix = 0;
            #pragma unroll
            for (int s = 1; s < 4; s++)
                if (logit[s] > mx) { mx = logit[s]; ix = s; }

            float ev[4], sum = 0.f;
            #pragma unroll
            for (int s = 0; s < 4; s++) { ev[s] = expf(logit[s] - mx); sum += ev[s]; }
            float inv = 1.f / sum;
            #pragma unroll
            for (int s = 0; s < 4; s++) wt[e][s] = ev[s] * inv;

            float s0 = inv * clw0 + clb0;   // wt[ix] == inv exactly
            float s1 = inv * clw1 + clb1;
            pc[e] = (s1 > s0) ? 1 : 0;
            float cw[4];
            #pragma unroll
            for (int s = 0; s < 4; s++)
                cw[s] = pc[e] ? ((s == ix) ? 1.f : 0.f) : wt[e][s];
            perm4f(cw, cwp[e], p);   // cwp[s] = cw[s ^ p] matches memreg slot s
        }

        // g = sum_s cwp[s]*memreg[s] + grp ; el = g * it
        float4 gv[2][2], el[2][2];
        {
            const float4* gA = (const float4*)(group_emb + (size_t)gidA * DIM);
            const float4* gB = (const float4*)(group_emb + (size_t)gidB * DIM);
            #pragma unroll
            for (int e = 0; e < 2; e++) {
                const float4* grow = (e == 0) ? gA : gB;
                #pragma unroll
                for (int g = 0; g < 2; g++) {
                    float4 grp = grow[g * 32 + lane];
                    float4 v;
                    v.x = cwp[e][0]*mem[e][0][g].x + cwp[e][1]*mem[e][1][g].x + cwp[e][2]*mem[e][2][g].x + cwp[e][3]*mem[e][3][g].x;
                    v.y = cwp[e][0]*mem[e][0][g].y + cwp[e][1]*mem[e][1][g].y + cwp[e][2]*mem[e][2][g].y + cwp[e][3]*mem[e][3][g].y;
                    v.z = cwp[e][0]*mem[e][0][g].z + cwp[e][1]*mem[e][1][g].z + cwp[e][2]*mem[e][2][g].z + cwp[e][3]*mem[e][3][g].z;
                    v.w = cwp[e][0]*mem[e][0][g].w + cwp[e][1]*mem[e][1][g].w + cwp[e][2]*mem[e][2][g].w + cwp[e][3]*mem[e][3][g].w;
                    v.x += grp.x; v.y += grp.y; v.z += grp.z; v.w += grp.w;
                    gv[e][g] = v;
                    el[e][g] = make_float4(v.x * it[e][g].x, v.y * it[e][g].y,
                                           v.z * it[e][g].z, v.w * it[e][g].w);
                }
            }
        }

        // ---- prediction MLP: slot k holds value (k ^ l7); SEL-free fold8 ----
        float A20[8], A21[8];
        #pragma unroll
        for (int k = 0; k < 8; k++) {
            const int kk = k ^ l7;   // weight row this lane reads for slot k
            float acc0 = 0.f, acc1 = 0.f;
            #pragma unroll
            for (int r = 0; r < 3; r++) {
                uint4 u = *(const uint4*)(swp + (kk * 3 + r) * 256 + lane * 8);
                const __nv_bfloat162* h2 = (const __nv_bfloat162*)&u;
                float2 p0 = __bfloat1622float2(h2[0]);
                float2 p1 = __bfloat1622float2(h2[1]);
                float2 p2 = __bfloat1622float2(h2[2]);
                float2 p3 = __bfloat1622float2(h2[3]);
                #pragma unroll
                for (int e = 0; e < 2; e++) {
                    float4 v0 = (r == 0) ? el[e][0] : (r == 1) ? gv[e][0] : it[e][0];
                    float4 v1 = (r == 0) ? el[e][1] : (r == 1) ? gv[e][1] : it[e][1];
                    float a = p0.x * v0.x + p0.y * v0.y + p1.x * v0.z + p1.y * v0.w
                            + p2.x * v1.x + p2.y * v1.y + p3.x * v1.z + p3.y * v1.w;
                    if (e == 0) acc0 += a; else acc1 += a;
                }
            }
            A20[k] = acc0;
            A21[k] = acc1;
        }

        float y[2];
        #pragma unroll
        for (int e = 0; e < 2; e++) {
            float v = fold8x(e == 0 ? A20 : A21);   // full acc for k = lane&7
            float hz = fmaxf(v + pbk, 0.f) * pwk;
            hz += __shfl_xor_sync(FULLM, hz, 1);
            hz += __shfl_xor_sync(FULLM, hz, 2);
            hz += __shfl_xor_sync(FULLM, hz, 4);
            float z = hz + pb2;
            y[e] = 1.f / (1.f + expf(-z));
        }

        if (lane < 2) {
            const int e = lane;
            const int b = 2 * pp + e;
            out[b] = y[e];
            *(float4*)(out + BATCH + 4 * b) = make_float4(wt[e][0], wt[e][1], wt[e][2], wt[e][3]);
            out[5 * BATCH + b] = (float)pc[e];
        }
    }
}

extern "C" void kernel_launch(void* const* d_in, const int* in_sizes, int n_in,
                              void* d_out, int out_size)
{
    (void)in_sizes; (void)n_in; (void)out_size;
    cudaFuncSetAttribute(agree_kernel,
                         cudaFuncAttributeMaxDynamicSharedMemorySize, SMEM_BYTES);
    agree_kernel<<<444, 128, SMEM_BYTES>>>(
        (const int*)d_in[0],  (const int*)d_in[1],  (const int*)d_in[2],
        (const float*)d_in[3], (const float*)d_in[4], (const float*)d_in[5],
        (const float*)d_in[6], (const float*)d_in[7], (const float*)d_in[8],
        (const float*)d_in[9], (const float*)d_in[10], (const float*)d_in[11],
        (const float*)d_in[12], (const float*)d_in[13], (const float*)d_in[14],
        (const float*)d_in[15],
        (float*)d_out);
}

// round 7
// speedup vs baseline: 1.3431x; 1.0382x over previous
#include <cuda_runtime.h>
#include <cuda_bf16.h>
#include <math.h>

#define BATCH 65536
#define NPAIR 32768
#define DIM   256
#define FULLM 0xffffffffu

// smem: att_w1 transposed [16][512] fp32 (32768B) + pred_w1 packed bf16 (12288B)
#define SW1_FLOATS (16 * 512)
#define SWP_HALFS  (8 * 3 * 256)
#define SMEM_BYTES (SW1_FLOATS * 4 + SWP_HALFS * 2)   // 45056 B

typedef unsigned long long u64;

// ---- packed f32x2 (FFMA2) helpers: operands are (lo,hi) f32 pairs in a u64 ----
__device__ __forceinline__ u64 ffma2(u64 a, u64 b, u64 c) {
    u64 d; asm("fma.rn.f32x2 %0,%1,%2,%3;" : "=l"(d) : "l"(a), "l"(b), "l"(c)); return d;
}
__device__ __forceinline__ u64 fadd2(u64 a, u64 b) {
    u64 d; asm("add.rn.f32x2 %0,%1,%2;" : "=l"(d) : "l"(a), "l"(b)); return d;
}
__device__ __forceinline__ u64 fmul2(u64 a, u64 b) {
    u64 d; asm("mul.rn.f32x2 %0,%1,%2;" : "=l"(d) : "l"(a), "l"(b)); return d;
}
__device__ __forceinline__ u64 dup2(float x) {
    u64 r; asm("mov.b64 %0,{%1,%1};" : "=l"(r) : "f"(x)); return r;
}
// horizontal add of the two f32 halves (unpack is register aliasing -> 1 FADD)
__device__ __forceinline__ float hadd2(u64 p) {
    float x, y; asm("mov.b64 {%0,%1},%2;" : "=f"(x), "=f"(y) : "l"(p));
    return x + y;
}
// bf16x2 (packed in u32) -> f32x2 pair, exact, via bit shifts
__device__ __forceinline__ u64 bf2f2(unsigned int u) {
    unsigned int lo = u << 16, hi = u & 0xffff0000u;
    u64 r; asm("mov.b64 %0,{%1,%2};" : "=l"(r) : "r"(lo), "r"(hi)); return r;
}

// SEL-free fold: A[i] holds partial of value (i ^ (lane&15)).
__device__ __forceinline__ float fold16x(float* A) {
    #pragma unroll
    for (int d = 8; d >= 1; d >>= 1)
        #pragma unroll
        for (int i = 0; i < d; i++)
            A[i] += __shfl_xor_sync(FULLM, A[i + d], d);
    float v = A[0];
    v += __shfl_xor_sync(FULLM, v, 16);
    return v;
}
// SEL-free fold: A[i] holds partial of value (i ^ (lane&7)).
__device__ __forceinline__ float fold8x(float* A) {
    #pragma unroll
    for (int d = 4; d >= 1; d >>= 1)
        #pragma unroll
        for (int i = 0; i < d; i++)
            A[i] += __shfl_xor_sync(FULLM, A[i + d], d);
    float v = A[0];
    v += __shfl_xor_sync(FULLM, v, 8);
    v += __shfl_xor_sync(FULLM, v, 16);
    return v;
}

__device__ __forceinline__ void perm4i(const int* in, int* out, int p) {
    int t0 = (p & 1) ? in[1] : in[0];
    int t1 = (p & 1) ? in[0] : in[1];
    int t2 = (p & 1) ? in[3] : in[2];
    int t3 = (p & 1) ? in[2] : in[3];
    out[0] = (p & 2) ? t2 : t0;
    out[1] = (p & 2) ? t3 : t1;
    out[2] = (p & 2) ? t0 : t2;
    out[3] = (p & 2) ? t1 : t3;
}
__device__ __forceinline__ void perm4f(const float* in, float* out, int p) {
    float t0 = (p & 1) ? in[1] : in[0];
    float t1 = (p & 1) ? in[0] : in[1];
    float t2 = (p & 1) ? in[3] : in[2];
    float t3 = (p & 1) ? in[2] : in[3];
    out[0] = (p & 2) ? t2 : t0;
    out[1] = (p & 2) ? t3 : t1;
    out[2] = (p & 2) ? t0 : t2;
    out[3] = (p & 2) ? t1 : t3;
}

__global__ __launch_bounds__(128, 3)
void agree_kernel(
    const int*   __restrict__ group_inputs,
    const int*   __restrict__ item_inputs,
    const int*   __restrict__ group_members,
    const float* __restrict__ user_emb,
    const float* __restrict__ item_emb,
    const float* __restrict__ group_emb,
    const float* __restrict__ att_w1,
    const float* __restrict__ att_b1,
    const float* __restrict__ att_w2,
    const float* __restrict__ att_b2,
    const float* __restrict__ cls_w,
    const float* __restrict__ cls_b,
    const float* __restrict__ pred_w1,
    const float* __restrict__ pred_b1,
    const float* __restrict__ pred_w2,
    const float* __restrict__ pred_b2,
    float*       __restrict__ out)
{
    extern __shared__ float sm[];
    float* sw1 = sm;                                        // [16][512] fp32
    __nv_bfloat16* swp = (__nv_bfloat16*)(sm + SW1_FLOATS); // packed bf16

    const int tid = threadIdx.x;

    for (int i = tid; i < 512 * 16; i += blockDim.x) {
        int d = i >> 4, f = i & 15;
        sw1[f * 512 + d] = att_w1[i];
    }
    // pred_w1 bf16 packed: half index = k*768 + r*256 + lane*8 + ii
    // src j = r*256 + (ii>=4 ? 128 : 0) + 4*lane + (ii&3), value pred_w1[j*8+k]
    for (int i = tid; i < SWP_HALFS; i += blockDim.x) {
        int k   = i / 768;
        int rem = i - k * 768;
        int r   = rem >> 8;
        int qq  = rem & 255;
        int ln  = qq >> 3;
        int ii  = qq & 7;
        int j   = r * 256 + ((ii & 4) ? 128 : 0) + 4 * ln + (ii & 3);
        swp[i] = __float2bfloat16(pred_w1[j * 8 + k]);
    }
    __syncthreads();

    const int lane  = tid & 31;
    const int gwarp = blockIdx.x * 4 + (tid >> 5);
    const int nwarp = gridDim.x * 4;

    const int q  = lane & 3;           // f-permutation within chunk
    const int p  = (lane >> 2) & 3;    // member (s) permutation
    const int l7 = lane & 7;           // pred k slot base
    const int qs = q << 9;             // q*512 for XOR addressing

    float b1c[4], w2c[4];
    #pragma unroll
    for (int c = 0; c < 4; c++) {
        b1c[c] = __ldg(att_b1 + c * 4 + q);
        w2c[c] = __ldg(att_w2 + c * 4 + q);
    }
    const float pbk  = __ldg(pred_b1 + l7);
    const float pwk  = __ldg(pred_w2 + l7);
    const float b2v  = __ldg(att_b2);
    const float clw0 = __ldg(cls_w), clw1 = __ldg(cls_w + 1);
    const float clb0 = __ldg(cls_b), clb1 = __ldg(cls_b + 1);
    const float pb2  = __ldg(pred_b2);

    for (int pp = gwarp; pp < NPAIR; pp += nwarp) {
        const int b0 = 2 * pp, b1 = 2 * pp + 1;
        const int gidA = group_inputs[b0], gidB = group_inputs[b1];
        const int iidA = item_inputs[b0],  iidB = item_inputs[b1];

        // member ids, permuted so register slot s holds member (s ^ p)
        int mpA[4], mpB[4];
        {
            const int4 mA = *(const int4*)(group_members + gidA * 4);
            const int4 mB = *(const int4*)(group_members + gidB * 4);
            int rawA[4] = {mA.x, mA.y, mA.z, mA.w};
            int rawB[4] = {mB.x, mB.y, mB.z, mB.w};
            perm4i(rawA, mpA, p);
            perm4i(rawB, mpB, p);
        }

        // gather rows as f32x2 pairs; lane owns dims {4l..4l+3, 128+4l..128+4l+3}
        u64 pmem[2][4][4], pit[2][4];
        #pragma unroll
        for (int s = 0; s < 4; s++) {
            const ulonglong2* rA = (const ulonglong2*)(user_emb + (size_t)mpA[s] * DIM);
            const ulonglong2* rB = (const ulonglong2*)(user_emb + (size_t)mpB[s] * DIM);
            ulonglong2 a0 = rA[lane], a1 = rA[32 + lane];
            ulonglong2 c0 = rB[lane], c1 = rB[32 + lane];
            pmem[0][s][0] = a0.x; pmem[0][s][1] = a0.y; pmem[0][s][2] = a1.x; pmem[0][s][3] = a1.y;
            pmem[1][s][0] = c0.x; pmem[1][s][1] = c0.y; pmem[1][s][2] = c1.x; pmem[1][s][3] = c1.y;
        }
        {
            const ulonglong2* iA = (const ulonglong2*)(item_emb + (size_t)iidA * DIM);
            const ulonglong2* iB = (const ulonglong2*)(item_emb + (size_t)iidB * DIM);
            ulonglong2 a0 = iA[lane], a1 = iA[32 + lane];
            ulonglong2 c0 = iB[lane], c1 = iB[32 + lane];
            pit[0][0] = a0.x; pit[0][1] = a0.y; pit[0][2] = a1.x; pit[0][3] = a1.y;
            pit[1][0] = c0.x; pit[1][1] = c0.y; pit[1][2] = c1.x; pit[1][3] = c1.y;
        }

        // ---- attention MLP: FFMA2 over dim pairs, XOR-permuted slots, SEL-free folds ----
        float logit_loc[2] = {b2v, b2v};
        #pragma unroll
        for (int c = 0; c < 4; c++) {
            float A0[16], A1[16];
            #pragma unroll
            for (int fi = 0; fi < 4; fi++) {
                // lane reads weight row f = c*4 + (fi ^ q)
                const float* wrow = sw1 + c * 2048 + ((fi << 9) ^ qs) + 4 * lane;
                ulonglong2 wm0 = *(const ulonglong2*)(wrow);         // member dims 4l..+3
                ulonglong2 wm1 = *(const ulonglong2*)(wrow + 128);   // member dims 128+4l..
                ulonglong2 wi0 = *(const ulonglong2*)(wrow + 256);   // item dims
                ulonglong2 wi1 = *(const ulonglong2*)(wrow + 384);

                u64 t0 = fmul2(pit[0][0], wi0.x);
                t0 = ffma2(pit[0][1], wi0.y, t0);
                t0 = ffma2(pit[0][2], wi1.x, t0);
                t0 = ffma2(pit[0][3], wi1.y, t0);
                u64 t1 = fmul2(pit[1][0], wi0.x);
                t1 = ffma2(pit[1][1], wi0.y, t1);
                t1 = ffma2(pit[1][2], wi1.x, t1);
                t1 = ffma2(pit[1][3], wi1.y, t1);

                #pragma unroll
                for (int s = 0; s < 4; s++) {
                    u64 a = t0;
                    a = ffma2(pmem[0][s][0], wm0.x, a);
                    a = ffma2(pmem[0][s][1], wm0.y, a);
                    a = ffma2(pmem[0][s][2], wm1.x, a);
                    a = ffma2(pmem[0][s][3], wm1.y, a);
                    A0[s * 4 + fi] = hadd2(a);
                    u64 b = t1;
                    b = ffma2(pmem[1][s][0], wm0.x, b);
                    b = ffma2(pmem[1][s][1], wm0.y, b);
                    b = ffma2(pmem[1][s][2], wm1.x, b);
                    b = ffma2(pmem[1][s][3], wm1.y, b);
                    A1[s * 4 + fi] = hadd2(b);
                }
            }
            {
                float r0 = fold16x(A0);
                float cv = fmaxf(r0 + b1c[c], 0.f) * w2c[c];
                cv += __shfl_xor_sync(FULLM, cv, 1);
                cv += __shfl_xor_sync(FULLM, cv, 2);
                logit_loc[0] += cv;
            }
            {
                float r1 = fold16x(A1);
                float cv = fmaxf(r1 + b1c[c], 0.f) * w2c[c];
                cv += __shfl_xor_sync(FULLM, cv, 1);
                cv += __shfl_xor_sync(FULLM, cv, 2);
                logit_loc[1] += cv;
            }
        }

        // softmax / argmax / classifier per element (lane s*4 holds member s)
        float wt[2][4];
        int   pc[2];
        float cwp[2][4];
        #pragma unroll
        for (int e = 0; e < 2; e++) {
            float logit[4];
            #pragma unroll
            for (int s = 0; s < 4; s++)
                logit[s] = __shfl_sync(FULLM, logit_loc[e], s * 4);

            float mx = logit[0]; int ix = 0;
            #pragma unroll
            for (int s = 1; s < 4; s++)
                if (logit[s] > mx) { mx = logit[s]; ix = s; }

            float ev[4], sum = 0.f;
            #pragma unroll
            for (int s = 0; s < 4; s++) { ev[s] = expf(logit[s] - mx); sum += ev[s]; }
            float inv = 1.f / sum;
            #pragma unroll
            for (int s = 0; s < 4; s++) wt[e][s] = ev[s] * inv;

            float s0 = inv * clw0 + clb0;   // wt[ix] == inv exactly
            float s1 = inv * clw1 + clb1;
            pc[e] = (s1 > s0) ? 1 : 0;
            float cw[4];
            #pragma unroll
            for (int s = 0; s < 4; s++)
                cw[s] = pc[e] ? ((s == ix) ? 1.f : 0.f) : wt[e][s];
            perm4f(cw, cwp[e], p);   // cwp[s] = cw[s ^ p] matches pmem slot s
        }

        // ---- epilogue packed: g = sum_s cwp*mem + grp ; el = g*it ----
        u64 pgv[2][4], pel[2][4];
        {
            const ulonglong2* gA = (const ulonglong2*)(group_emb + (size_t)gidA * DIM);
            const ulonglong2* gB = (const ulonglong2*)(group_emb + (size_t)gidB * DIM);
            #pragma unroll
            for (int e = 0; e < 2; e++) {
                u64 c0 = dup2(cwp[e][0]), c1 = dup2(cwp[e][1]);
                u64 c2 = dup2(cwp[e][2]), c3 = dup2(cwp[e][3]);
                const ulonglong2* grow = (e == 0) ? gA : gB;
                ulonglong2 g0 = grow[lane], g1 = grow[32 + lane];
                u64 grp[4] = {g0.x, g0.y, g1.x, g1.y};
                #pragma unroll
                for (int j = 0; j < 4; j++) {
                    u64 t = fmul2(pmem[e][0][j], c0);
                    t = ffma2(pmem[e][1][j], c1, t);
                    t = ffma2(pmem[e][2][j], c2, t);
                    t = ffma2(pmem[e][3][j], c3, t);
                    t = fadd2(t, grp[j]);
                    pgv[e][j] = t;
                    pel[e][j] = fmul2(t, pit[e][j]);
                }
            }
        }

        // ---- prediction MLP: FFMA2, slot k holds value (k ^ l7), SEL-free fold8 ----
        float A20[8], A21[8];
        #pragma unroll
        for (int k = 0; k < 8; k++) {
            const int kk = k ^ l7;
            u64 a0 = 0ull, a1 = 0ull;   // (0,0)
            #pragma unroll
            for (int r = 0; r < 3; r++) {
                const u64* v0 = (r == 0) ? pel[0] : (r == 1) ? pgv[0] : pit[0];
                const u64* v1 = (r == 0) ? pel[1] : (r == 1) ? pgv[1] : pit[1];
                uint4 u = *(const uint4*)(swp + (kk * 3 + r) * 256 + lane * 8);
                u64 w0 = bf2f2(u.x), w1 = bf2f2(u.y), w2 = bf2f2(u.z), w3 = bf2f2(u.w);
                a0 = ffma2(v0[0], w0, a0);
                a0 = ffma2(v0[1], w1, a0);
                a0 = ffma2(v0[2], w2, a0);
                a0 = ffma2(v0[3], w3, a0);
                a1 = ffma2(v1[0], w0, a1);
                a1 = ffma2(v1[1], w1, a1);
                a1 = ffma2(v1[2], w2, a1);
                a1 = ffma2(v1[3], w3, a1);
            }
            A20[k] = hadd2(a0);
            A21[k] = hadd2(a1);
        }

        float y[2];
        #pragma unroll
        for (int e = 0; e < 2; e++) {
            float v = fold8x(e == 0 ? A20 : A21);   // full acc for k = lane&7
            float hz = fmaxf(v + pbk, 0.f) * pwk;
            hz += __shfl_xor_sync(FULLM, hz, 1);
            hz += __shfl_xor_sync(FULLM, hz, 2);
            hz += __shfl_xor_sync(FULLM, hz, 4);
            float z = hz + pb2;
            y[e] = 1.f / (1.f + expf(-z));
        }

        if (lane < 2) {
            const int e = lane;
            const int b = 2 * pp + e;
            out[b] = y[e];
            *(float4*)(out + BATCH + 4 * b) = make_float4(wt[e][0], wt[e][1], wt[e][2], wt[e][3]);
            out[5 * BATCH + b] = (float)pc[e];
        }
    }
}

extern "C" void kernel_launch(void* const* d_in, const int* in_sizes, int n_in,
                              void* d_out, int out_size)
{
    (void)in_sizes; (void)n_in; (void)out_size;
    cudaFuncSetAttribute(agree_kernel,
                         cudaFuncAttributeMaxDynamicSharedMemorySize, SMEM_BYTES);
    agree_kernel<<<444, 128, SMEM_BYTES>>>(
        (const int*)d_in[0],  (const int*)d_in[1],  (const int*)d_in[2],
        (const float*)d_in[3], (const float*)d_in[4], (const float*)d_in[5],
        (const float*)d_in[6], (const float*)d_in[7], (const float*)d_in[8],
        (const float*)d_in[9], (const float*)d_in[10], (const float*)d_in[11],
        (const float*)d_in[12], (const float*)d_in[13], (const float*)d_in[14],
        (const float*)d_in[15],
        (float*)d_out);
}

// round 8
// speedup vs baseline: 1.4865x; 1.1067x over previous
#include <cuda_runtime.h>
#include <cuda_bf16.h>
#include <math.h>

#define BATCH 65536
#define NPAIR 32768
#define DIM   256
#define FULLM 0xffffffffu

// smem: att_w1 transposed [16][512] fp32 (32768B) + pred_w1 packed bf16 (12288B)
#define SW1_FLOATS (16 * 512)
#define SWP_HALFS  (8 * 3 * 256)
#define SMEM_BYTES (SW1_FLOATS * 4 + SWP_HALFS * 2)   // 45056 B

typedef unsigned long long u64;

// ---- packed f32x2 (FFMA2) helpers ----
__device__ __forceinline__ u64 ffma2(u64 a, u64 b, u64 c) {
    u64 d; asm("fma.rn.f32x2 %0,%1,%2,%3;" : "=l"(d) : "l"(a), "l"(b), "l"(c)); return d;
}
__device__ __forceinline__ u64 fadd2(u64 a, u64 b) {
    u64 d; asm("add.rn.f32x2 %0,%1,%2;" : "=l"(d) : "l"(a), "l"(b)); return d;
}
__device__ __forceinline__ u64 fmul2(u64 a, u64 b) {
    u64 d; asm("mul.rn.f32x2 %0,%1,%2;" : "=l"(d) : "l"(a), "l"(b)); return d;
}
__device__ __forceinline__ u64 dup2(float x) {
    u64 r; asm("mov.b64 %0,{%1,%1};" : "=l"(r) : "f"(x)); return r;
}
__device__ __forceinline__ float hadd2(u64 p) {
    float x, y; asm("mov.b64 {%0,%1},%2;" : "=f"(x), "=f"(y) : "l"(p));
    return x + y;
}
__device__ __forceinline__ u64 bf2f2(unsigned int u) {
    unsigned int lo = u << 16, hi = u & 0xffff0000u;
    u64 r; asm("mov.b64 %0,{%1,%2};" : "=l"(r) : "r"(lo), "r"(hi)); return r;
}
__device__ __forceinline__ void pfl2(const void* p) {
    asm volatile("prefetch.global.L2 [%0];" :: "l"(p));
}

// SEL-free folds (slot i holds value i ^ (lane&mask))
__device__ __forceinline__ float fold16x(float* A) {
    #pragma unroll
    for (int d = 8; d >= 1; d >>= 1)
        #pragma unroll
        for (int i = 0; i < d; i++)
            A[i] += __shfl_xor_sync(FULLM, A[i + d], d);
    float v = A[0];
    v += __shfl_xor_sync(FULLM, v, 16);
    return v;
}
__device__ __forceinline__ float fold8x(float* A) {
    #pragma unroll
    for (int d = 4; d >= 1; d >>= 1)
        #pragma unroll
        for (int i = 0; i < d; i++)
            A[i] += __shfl_xor_sync(FULLM, A[i + d], d);
    float v = A[0];
    v += __shfl_xor_sync(FULLM, v, 8);
    v += __shfl_xor_sync(FULLM, v, 16);
    return v;
}

__device__ __forceinline__ void perm4i(const int* in, int* out, int p) {
    int t0 = (p & 1) ? in[1] : in[0];
    int t1 = (p & 1) ? in[0] : in[1];
    int t2 = (p & 1) ? in[3] : in[2];
    int t3 = (p & 1) ? in[2] : in[3];
    out[0] = (p & 2) ? t2 : t0;
    out[1] = (p & 2) ? t3 : t1;
    out[2] = (p & 2) ? t0 : t2;
    out[3] = (p & 2) ? t1 : t3;
}
__device__ __forceinline__ void perm4f(const float* in, float* out, int p) {
    float t0 = (p & 1) ? in[1] : in[0];
    float t1 = (p & 1) ? in[0] : in[1];
    float t2 = (p & 1) ? in[3] : in[2];
    float t3 = (p & 1) ? in[2] : in[3];
    out[0] = (p & 2) ? t2 : t0;
    out[1] = (p & 2) ? t3 : t1;
    out[2] = (p & 2) ? t0 : t2;
    out[3] = (p & 2) ? t1 : t3;
}

__global__ __launch_bounds__(128, 3)
void agree_kernel(
    const int*   __restrict__ group_inputs,
    const int*   __restrict__ item_inputs,
    const int*   __restrict__ group_members,
    const float* __restrict__ user_emb,
    const float* __restrict__ item_emb,
    const float* __restrict__ group_emb,
    const float* __restrict__ att_w1,
    const float* __restrict__ att_b1,
    const float* __restrict__ att_w2,
    const float* __restrict__ att_b2,
    const float* __restrict__ cls_w,
    const float* __restrict__ cls_b,
    const float* __restrict__ pred_w1,
    const float* __restrict__ pred_b1,
    const float* __restrict__ pred_w2,
    const float* __restrict__ pred_b2,
    float*       __restrict__ out)
{
    extern __shared__ float sm[];
    float* sw1 = sm;                                        // [16][512] fp32
    __nv_bfloat16* swp = (__nv_bfloat16*)(sm + SW1_FLOATS); // packed bf16

    const int tid = threadIdx.x;

    for (int i = tid; i < 512 * 16; i += blockDim.x) {
        int d = i >> 4, f = i & 15;
        sw1[f * 512 + d] = att_w1[i];
    }
    for (int i = tid; i < SWP_HALFS; i += blockDim.x) {
        int k   = i / 768;
        int rem = i - k * 768;
        int r   = rem >> 8;
        int qq  = rem & 255;
        int ln  = qq >> 3;
        int ii  = qq & 7;
        int j   = r * 256 + ((ii & 4) ? 128 : 0) + 4 * ln + (ii & 3);
        swp[i] = __float2bfloat16(pred_w1[j * 8 + k]);
    }
    __syncthreads();

    const int lane  = tid & 31;
    const int gwarp = blockIdx.x * 4 + (tid >> 5);
    const int nwarp = gridDim.x * 4;

    const int q  = lane & 3;
    const int p  = (lane >> 2) & 3;
    const int l7 = lane & 7;
    const int qs = q << 9;

    float b1c[4], w2c[4];
    #pragma unroll
    for (int c = 0; c < 4; c++) {
        b1c[c] = __ldg(att_b1 + c * 4 + q);
        w2c[c] = __ldg(att_w2 + c * 4 + q);
    }
    const float pbk  = __ldg(pred_b1 + l7);
    const float pwk  = __ldg(pred_w2 + l7);
    const float b2v  = __ldg(att_b2);
    const float clw0 = __ldg(cls_w), clw1 = __ldg(cls_w + 1);
    const float clb0 = __ldg(cls_b), clb1 = __ldg(cls_b + 1);
    const float pb2  = __ldg(pred_b2);

    // ---- software-pipelined index chain: prologue load for first iteration ----
    int gidA = group_inputs[2 * gwarp];
    int gidB = group_inputs[2 * gwarp + 1];
    int iidA = item_inputs[2 * gwarp];
    int iidB = item_inputs[2 * gwarp + 1];
    int4 mA = *(const int4*)(group_members + gidA * 4);
    int4 mB = *(const int4*)(group_members + gidB * 4);

    for (int pp = gwarp; pp < NPAIR; pp += nwarp) {
        // permute current member ids: slot s holds member (s ^ p)
        int mpA[4], mpB[4];
        {
            int rawA[4] = {mA.x, mA.y, mA.z, mA.w};
            int rawB[4] = {mB.x, mB.y, mB.z, mB.w};
            perm4i(rawA, mpA, p);
            perm4i(rawB, mpB, p);
        }

        // gather current rows (addresses warm in L2 from last iteration's prefetch)
        u64 pmem[2][4][4], pit[2][4];
        #pragma unroll
        for (int s = 0; s < 4; s++) {
            const ulonglong2* rA = (const ulonglong2*)(user_emb + (size_t)mpA[s] * DIM);
            const ulonglong2* rB = (const ulonglong2*)(user_emb + (size_t)mpB[s] * DIM);
            ulonglong2 a0 = rA[lane], a1 = rA[32 + lane];
            ulonglong2 c0 = rB[lane], c1 = rB[32 + lane];
            pmem[0][s][0] = a0.x; pmem[0][s][1] = a0.y; pmem[0][s][2] = a1.x; pmem[0][s][3] = a1.y;
            pmem[1][s][0] = c0.x; pmem[1][s][1] = c0.y; pmem[1][s][2] = c1.x; pmem[1][s][3] = c1.y;
        }
        {
            const ulonglong2* iA = (const ulonglong2*)(item_emb + (size_t)iidA * DIM);
            const ulonglong2* iB = (const ulonglong2*)(item_emb + (size_t)iidB * DIM);
            ulonglong2 a0 = iA[lane], a1 = iA[32 + lane];
            ulonglong2 c0 = iB[lane], c1 = iB[32 + lane];
            pit[0][0] = a0.x; pit[0][1] = a0.y; pit[0][2] = a1.x; pit[0][3] = a1.y;
            pit[1][0] = c0.x; pit[1][1] = c0.y; pit[1][2] = c1.x; pit[1][3] = c1.y;
        }

        // early-issue next iteration's index chain (resolves under attention)
        const int ppn = pp + nwarp;
        const bool hn  = ppn < NPAIR;
        const int bn  = hn ? 2 * ppn : 2 * pp;
        int gidAn = group_inputs[bn];
        int gidBn = group_inputs[bn + 1];
        int iidAn = item_inputs[bn];
        int iidBn = item_inputs[bn + 1];
        int4 mAn = *(const int4*)(group_members + gidAn * 4);
        int4 mBn = *(const int4*)(group_members + gidBn * 4);

        // ---- attention MLP: FFMA2 over dim pairs, XOR-permuted slots ----
        float logit_loc[2] = {b2v, b2v};
        #pragma unroll
        for (int c = 0; c < 4; c++) {
            float A0[16], A1[16];
            #pragma unroll
            for (int fi = 0; fi < 4; fi++) {
                const float* wrow = sw1 + c * 2048 + ((fi << 9) ^ qs) + 4 * lane;
                ulonglong2 wm0 = *(const ulonglong2*)(wrow);
                ulonglong2 wm1 = *(const ulonglong2*)(wrow + 128);
                ulonglong2 wi0 = *(const ulonglong2*)(wrow + 256);
                ulonglong2 wi1 = *(const ulonglong2*)(wrow + 384);

                u64 t0 = fmul2(pit[0][0], wi0.x);
                t0 = ffma2(pit[0][1], wi0.y, t0);
                t0 = ffma2(pit[0][2], wi1.x, t0);
                t0 = ffma2(pit[0][3], wi1.y, t0);
                u64 t1 = fmul2(pit[1][0], wi0.x);
                t1 = ffma2(pit[1][1], wi0.y, t1);
                t1 = ffma2(pit[1][2], wi1.x, t1);
                t1 = ffma2(pit[1][3], wi1.y, t1);

                #pragma unroll
                for (int s = 0; s < 4; s++) {
                    u64 a = t0;
                    a = ffma2(pmem[0][s][0], wm0.x, a);
                    a = ffma2(pmem[0][s][1], wm0.y, a);
                    a = ffma2(pmem[0][s][2], wm1.x, a);
                    a = ffma2(pmem[0][s][3], wm1.y, a);
                    A0[s * 4 + fi] = hadd2(a);
                    u64 b = t1;
                    b = ffma2(pmem[1][s][0], wm0.x, b);
                    b = ffma2(pmem[1][s][1], wm0.y, b);
                    b = ffma2(pmem[1][s][2], wm1.x, b);
                    b = ffma2(pmem[1][s][3], wm1.y, b);
                    A1[s * 4 + fi] = hadd2(b);
                }
            }
            {
                float r0 = fold16x(A0);
                float cv = fmaxf(r0 + b1c[c], 0.f) * w2c[c];
                cv += __shfl_xor_sync(FULLM, cv, 1);
                cv += __shfl_xor_sync(FULLM, cv, 2);
                logit_loc[0] += cv;
            }
            {
                float r1 = fold16x(A1);
                float cv = fmaxf(r1 + b1c[c], 0.f) * w2c[c];
                cv += __shfl_xor_sync(FULLM, cv, 1);
                cv += __shfl_xor_sync(FULLM, cv, 2);
                logit_loc[1] += cv;
            }
        }

        // prefetch next iteration's embedding rows into L2 (next ids arrived by now)
        if (hn) {
            int mn[8] = {mAn.x, mAn.y, mAn.z, mAn.w, mBn.x, mBn.y, mBn.z, mBn.w};
            #pragma unroll
            for (int s = 0; s < 8; s++) {
                const float* r = user_emb + (size_t)mn[s] * DIM + 4 * lane;
                pfl2(r); pfl2(r + 128);
            }
            const float* ra = item_emb + (size_t)iidAn * DIM + 4 * lane;
            const float* rb = item_emb + (size_t)iidBn * DIM + 4 * lane;
            pfl2(ra); pfl2(ra + 128);
            pfl2(rb); pfl2(rb + 128);
            const float* ga = group_emb + (size_t)gidAn * DIM + 4 * lane;
            const float* gb = group_emb + (size_t)gidBn * DIM + 4 * lane;
            pfl2(ga); pfl2(ga + 128);
            pfl2(gb); pfl2(gb + 128);
        }

        // softmax / argmax / classifier per element (lane s*4 holds member s)
        float wt[2][4];
        int   pc[2];
        float cwp[2][4];
        #pragma unroll
        for (int e = 0; e < 2; e++) {
            float logit[4];
            #pragma unroll
            for (int s = 0; s < 4; s++)
                logit[s] = __shfl_sync(FULLM, logit_loc[e], s * 4);

            float mx = logit[0]; int ix = 0;
            #pragma unroll
            for (int s = 1; s < 4; s++)
                if (logit[s] > mx) { mx = logit[s]; ix = s; }

            float ev[4], sum = 0.f;
            #pragma unroll
            for (int s = 0; s < 4; s++) { ev[s] = expf(logit[s] - mx); sum += ev[s]; }
            float inv = 1.f / sum;
            #pragma unroll
            for (int s = 0; s < 4; s++) wt[e][s] = ev[s] * inv;

            float s0 = inv * clw0 + clb0;   // wt[ix] == inv exactly
            float s1 = inv * clw1 + clb1;
            pc[e] = (s1 > s0) ? 1 : 0;
            float cw[4];
            #pragma unroll
            for (int s = 0; s < 4; s++)
                cw[s] = pc[e] ? ((s == ix) ? 1.f : 0.f) : wt[e][s];
            perm4f(cw, cwp[e], p);
        }

        // ---- epilogue packed: g = sum_s cwp*mem + grp ; el = g*it ----
        u64 pgv[2][4], pel[2][4];
        {
            const ulonglong2* gA = (const ulonglong2*)(group_emb + (size_t)gidA * DIM);
            const ulonglong2* gB = (const ulonglong2*)(group_emb + (size_t)gidB * DIM);
            #pragma unroll
            for (int e = 0; e < 2; e++) {
                u64 c0 = dup2(cwp[e][0]), c1 = dup2(cwp[e][1]);
                u64 c2 = dup2(cwp[e][2]), c3 = dup2(cwp[e][3]);
                const ulonglong2* grow = (e == 0) ? gA : gB;
                ulonglong2 g0 = grow[lane], g1 = grow[32 + lane];
                u64 grp[4] = {g0.x, g0.y, g1.x, g1.y};
                #pragma unroll
                for (int j = 0; j < 4; j++) {
                    u64 t = fmul2(pmem[e][0][j], c0);
                    t = ffma2(pmem[e][1][j], c1, t);
                    t = ffma2(pmem[e][2][j], c2, t);
                    t = ffma2(pmem[e][3][j], c3, t);
                    t = fadd2(t, grp[j]);
                    pgv[e][j] = t;
                    pel[e][j] = fmul2(t, pit[e][j]);
                }
            }
        }

        // ---- prediction MLP: FFMA2, slot k holds value (k ^ l7) ----
        float A20[8], A21[8];
        #pragma unroll
        for (int k = 0; k < 8; k++) {
            const int kk = k ^ l7;
            u64 a0 = 0ull, a1 = 0ull;
            #pragma unroll
            for (int r = 0; r < 3; r++) {
                const u64* v0 = (r == 0) ? pel[0] : (r == 1) ? pgv[0] : pit[0];
                const u64* v1 = (r == 0) ? pel[1] : (r == 1) ? pgv[1] : pit[1];
                uint4 u = *(const uint4*)(swp + (kk * 3 + r) * 256 + lane * 8);
                u64 w0 = bf2f2(u.x), w1 = bf2f2(u.y), w2 = bf2f2(u.z), w3 = bf2f2(u.w);
                a0 = ffma2(v0[0], w0, a0);
                a0 = ffma2(v0[1], w1, a0);
                a0 = ffma2(v0[2], w2, a0);
                a0 = ffma2(v0[3], w3, a0);
                a1 = ffma2(v1[0], w0, a1);
                a1 = ffma2(v1[1], w1, a1);
                a1 = ffma2(v1[2], w2, a1);
                a1 = ffma2(v1[3], w3, a1);
            }
            A20[k] = hadd2(a0);
            A21[k] = hadd2(a1);
        }

        float y[2];
        #pragma unroll
        for (int e = 0; e < 2; e++) {
            float v = fold8x(e == 0 ? A20 : A21);
            float hz = fmaxf(v + pbk, 0.f) * pwk;
            hz += __shfl_xor_sync(FULLM, hz, 1);
            hz += __shfl_xor_sync(FULLM, hz, 2);
            hz += __shfl_xor_sync(FULLM, hz, 4);
            float z = hz + pb2;
            y[e] = 1.f / (1.f + expf(-z));
        }

        if (lane < 2) {
            const int e = lane;
            const int b = 2 * pp + e;
            out[b] = y[e];
            *(float4*)(out + BATCH + 4 * b) = make_float4(wt[e][0], wt[e][1], wt[e][2], wt[e][3]);
            out[5 * BATCH + b] = (float)pc[e];
        }

        // rotate pipelined indices
        gidA = gidAn; gidB = gidBn; iidA = iidAn; iidB = iidBn;
        mA = mAn; mB = mBn;
    }
}

extern "C" void kernel_launch(void* const* d_in, const int* in_sizes, int n_in,
                              void* d_out, int out_size)
{
    (void)in_sizes; (void)n_in; (void)out_size;
    cudaFuncSetAttribute(agree_kernel,
                         cudaFuncAttributeMaxDynamicSharedMemorySize, SMEM_BYTES);
    agree_kernel<<<444, 128, SMEM_BYTES>>>(
        (const int*)d_in[0],  (const int*)d_in[1],  (const int*)d_in[2],
        (const float*)d_in[3], (const float*)d_in[4], (const float*)d_in[5],
        (const float*)d_in[6], (const float*)d_in[7], (const float*)d_in[8],
        (const float*)d_in[9], (const float*)d_in[10], (const float*)d_in[11],
        (const float*)d_in[12], (const float*)d_in[13], (const float*)d_in[14],
        (const float*)d_in[15],
        (float*)d_out);
}